// round 11
// baseline (speedup 1.0000x reference)
#include <cuda_runtime.h>
#include <cuda_fp16.h>

#define H 1024
#define W 1024
#define PLANES 24              // 8 * 3
#define THRAW 32               // raw output rows per tile
#define PACK 16                // row-pack stride (.x = r, .y = r+16)
#define TW 128                 // tile cols
#define RE 8                   // cols per thread
#define BX 16
#define BY 16                  // packed rows per tile
#define PROWS (BY + 3)         // 19
#define SCOLS (TW + 8)         // 136 half2 = 34 16B-chunks per row
#define NBX (W / TW)           // 8
#define NBY (H / THRAW)        // 32
#define NT (NBX * NBY * PLANES)       // 6144 tiles
#define GRIDB 740              // 148 SMs x 5 resident blocks: persistent grid
#define NGRP (PROWS * (TW / 4))       // 608 interior float4-groups
#define NHALO (PROWS * 8)             // 152 halo half2 entries

// Even/odd chunk de-interleave: physical slot i (0..31 interior) holds logical
// gmem float4 group QPERM(i). LDS window chunks become physically contiguous.
#define QPERM(i) (((i) < 16) ? (2 * (i) + 1) : (2 * ((i) - 16)))

__device__ float g_partials[GRIDB];
__device__ int g_ctr = 0;

// Window load from de-interleaved layout. Physical chunks: tx, 17+tx, tx+1, 18+tx
// hold logical chunks 2tx, 2tx+1, 2tx+2, 2tx+3 (cols 8tx..8tx+15).
#define LOADROW(wdst, srow, txv)                                                   \
    do {                                                                           \
        const float4* rowp = reinterpret_cast<const float4*>(&(srow)[0]);          \
        float4 v0 = rowp[(txv)];                                                   \
        float4 v1 = rowp[17 + (txv)];                                              \
        float4 v2 = rowp[(txv) + 1];                                               \
        float4 v3 = rowp[18 + (txv)];                                              \
        (wdst)[0] = *(__half2*)&v0.x;  (wdst)[1] = *(__half2*)&v0.y;               \
        (wdst)[2] = *(__half2*)&v0.z;  (wdst)[3] = *(__half2*)&v0.w;               \
        (wdst)[4] = *(__half2*)&v1.x;  (wdst)[5] = *(__half2*)&v1.y;               \
        (wdst)[6] = *(__half2*)&v1.z;  (wdst)[7] = *(__half2*)&v1.w;               \
        (wdst)[8] = *(__half2*)&v2.x;  (wdst)[9] = *(__half2*)&v2.y;               \
        (wdst)[10] = *(__half2*)&v2.z; (wdst)[11] = *(__half2*)&v2.w;              \
        (wdst)[12] = *(__half2*)&v3.x; (wdst)[13] = *(__half2*)&v3.y;              \
        (wdst)[14] = *(__half2*)&v3.z; (wdst)[15] = *(__half2*)&v3.w;              \
    } while (0)

// One interior prefetch sub-phase: group g = tid + OFF, OFF in {0, 256}.
// All sub-phases share registers aP/bP (sequenced by program order).
#define PREF_I(tt, OFF)                                                            \
    do {                                                                           \
        int px_ = (tt) & (NBX - 1), py_ = ((tt) >> 3) & (NBY - 1), pz_ = (tt) >> 8; \
        int txx = px_ * TW, tyy = py_ * THRAW;                                     \
        const float4* pp = reinterpret_cast<const float4*>(x + (size_t)pz_ * (H * W)); \
        int g = tid + (OFF);                                                       \
        int r = g >> 5, i = g & 31;                                                \
        int q = QPERM(i);                                                          \
        aP = pp[(((tyy + r) & (H - 1)) * (W / 4)) + (txx >> 2) + q];               \
        bP = pp[(((tyy + r + PACK) & (H - 1)) * (W / 4)) + (txx >> 2) + q];        \
    } while (0)

#define STORE_I(buf, OFF)                                                          \
    do {                                                                           \
        int g = tid + (OFF);                                                       \
        int r = g >> 5, i = g & 31;                                                \
        __half2 h0 = __floats2half2_rn(aP.x, bP.x);                                \
        __half2 h1 = __floats2half2_rn(aP.y, bP.y);                                \
        __half2 h2 = __floats2half2_rn(aP.z, bP.z);                                \
        __half2 h3 = __floats2half2_rn(aP.w, bP.w);                                \
        float4 st;                                                                 \
        st.x = *(float*)&h0; st.y = *(float*)&h1;                                  \
        st.z = *(float*)&h2; st.w = *(float*)&h3;                                  \
        *reinterpret_cast<float4*>(&s[buf][r][4 + 4 * i]) = st;                    \
    } while (0)

// Final sub-phase: interior groups [512, 608) (guard tid<96) + halo.
#define PREF_B(tt)                                                                 \
    do {                                                                           \
        int px_ = (tt) & (NBX - 1), py_ = ((tt) >> 3) & (NBY - 1), pz_ = (tt) >> 8; \
        int txx = px_ * TW, tyy = py_ * THRAW;                                     \
        const float* pl = x + (size_t)pz_ * (H * W);                               \
        const float4* pp = reinterpret_cast<const float4*>(pl);                    \
        if (tid < NGRP - 512) {                                                    \
            int g = tid + 512;                                                     \
            int r = g >> 5, i = g & 31;                                            \
            int q = QPERM(i);                                                      \
            aP = pp[(((tyy + r) & (H - 1)) * (W / 4)) + (txx >> 2) + q];           \
            bP = pp[(((tyy + r + PACK) & (H - 1)) * (W / 4)) + (txx >> 2) + q];    \
        }                                                                          \
        if (tid < NHALO) {                                                         \
            int r = tid >> 3, hcp = tid & 7;                                       \
            int c = (hcp < 4) ? hcp : (128 + hcp);                                 \
            int gc = (txx + c - 4) & (W - 1);                                      \
            pha = pl[(((tyy + r) & (H - 1)) * W) + gc];                            \
            phb = pl[(((tyy + r + PACK) & (H - 1)) * W) + gc];                     \
        }                                                                          \
    } while (0)

#define STORE_B(buf)                                                               \
    do {                                                                           \
        if (tid < NGRP - 512) {                                                    \
            int g = tid + 512;                                                     \
            int r = g >> 5, i = g & 31;                                            \
            __half2 h0 = __floats2half2_rn(aP.x, bP.x);                            \
            __half2 h1 = __floats2half2_rn(aP.y, bP.y);                            \
            __half2 h2 = __floats2half2_rn(aP.z, bP.z);                            \
            __half2 h3 = __floats2half2_rn(aP.w, bP.w);                            \
            float4 st;                                                             \
            st.x = *(float*)&h0; st.y = *(float*)&h1;                              \
            st.z = *(float*)&h2; st.w = *(float*)&h3;                              \
            *reinterpret_cast<float4*>(&s[buf][r][4 + 4 * i]) = st;                \
        }                                                                          \
        if (tid < NHALO) {                                                         \
            int r = tid >> 3, hcp = tid & 7;                                       \
            int c = (hcp < 4) ? hcp : (128 + hcp);                                 \
            s[buf][r][c] = __floats2half2_rn(pha, phb);                            \
        }                                                                          \
    } while (0)

// One k-row compute section.
#define KROW(row, DL0, DL1)                                                        \
    do {                                                                           \
        __half2 win[16];                                                           \
        LOADROW(win, s[cb][row], tx);                                              \
        _Pragma("unroll")                                                          \
        for (int dl = (DL0); dl <= (DL1); dl++) {                                  \
            _Pragma("unroll")                                                      \
            for (int e = 0; e < RE; e++) {                                         \
                __half2 d = __habs2(__hsub2(c2[e], win[4 + e + dl]));              \
                acc[e] = __hadd2(acc[e], d);                                       \
            }                                                                      \
        }                                                                          \
    } while (0)

__global__ __launch_bounds__(BX * BY, 5) void btv_kernel(const float* __restrict__ x,
                                                         float* __restrict__ out) {
    __shared__ __align__(16) __half2 s[2][PROWS][SCOLS];
    __shared__ float warp_sums[(BX * BY) / 32];
    __shared__ int s_last;

    const int tx = threadIdx.x;
    const int ty = threadIdx.y;
    const int tid = ty * BX + tx;

    float4 aP, bP;
    float pha = 0.0f, phb = 0.0f;
    float accf = 0.0f;

    int t = blockIdx.x;

    // Prologue: first tile into buffer 0 (sequential sub-phases, shared regs).
    PREF_I(t, 0);   STORE_I(0, 0);
    PREF_I(t, 256); STORE_I(0, 256);
    PREF_B(t);      STORE_B(0);
    __syncthreads();

    int cb = 0;
#pragma unroll 1
    for (; t < NT; t += GRIDB) {
        const int tn = t + GRIDB;
        const bool hn = (tn < NT);

        __half2 c2[RE];
        __half2 acc[RE];
#pragma unroll
        for (int e = 0; e < RE; e++) acc[e] = __floats2half2_rn(0.0f, 0.0f);

        if (hn) PREF_I(tn, 0);

        // k = 0: centers + dl = 1..3 (symmetry covers negatives)
        {
            __half2 win[16];
            LOADROW(win, s[cb][ty], tx);
#pragma unroll
            for (int e = 0; e < RE; e++) c2[e] = win[4 + e];
#pragma unroll
            for (int dl = 1; dl <= 3; dl++) {
#pragma unroll
                for (int e = 0; e < RE; e++) {
                    __half2 d = __habs2(__hsub2(c2[e], win[4 + e + dl]));
                    acc[e] = __hadd2(acc[e], d);
                }
            }
        }

        if (hn) { STORE_I(cb ^ 1, 0); PREF_I(tn, 256); }

        KROW(ty + 1, -3, 3);   // k = 1

        if (hn) { STORE_I(cb ^ 1, 256); PREF_B(tn); }

        KROW(ty + 2, -3, 3);   // k = 2

        if (hn) STORE_B(cb ^ 1);

        KROW(ty + 3, -3, 3);   // k = 3

        // Drain fp16 accumulators to fp32 per tile.
#pragma unroll
        for (int e = 0; e < RE; e++) {
            float2 f = __half22float2(acc[e]);
            accf += f.x + f.y;
        }

        if (hn) __syncthreads();
        cb ^= 1;
    }

    // ---- Block reduction ----
#pragma unroll
    for (int o = 16; o > 0; o >>= 1) accf += __shfl_down_sync(0xFFFFFFFFu, accf, o);

    const int lane = tid & 31;
    const int wid = tid >> 5;
    if (lane == 0) warp_sums[wid] = accf;
    __syncthreads();

    if (tid == 0) {
        float bsum = 0.0f;
#pragma unroll
        for (int i = 0; i < (BX * BY) / 32; i++) bsum += warp_sums[i];
        g_partials[blockIdx.x] = bsum;
        __threadfence();
        int done = atomicAdd(&g_ctr, 1);
        s_last = (done == GRIDB - 1) ? 1 : 0;
    }
    __syncthreads();

    // Last block reduces all partials (fixed order -> deterministic)
    if (s_last) {
        double td = 0.0;
        for (int i = tid; i < GRIDB; i += BX * BY) td += (double)g_partials[i];
#pragma unroll
        for (int o = 16; o > 0; o >>= 1) td += __shfl_down_sync(0xFFFFFFFFu, td, o);
        __shared__ double sm[(BX * BY) / 32];
        if (lane == 0) sm[wid] = td;
        __syncthreads();
        if (tid == 0) {
            double r = 0.0;
#pragma unroll
            for (int i = 0; i < (BX * BY) / 32; i++) r += sm[i];
            // symmetry factor 2; WEIGHT=0.1; N = 24*1024*1024
            out[0] = (float)(r * (0.2 / 25165824.0));
            atomicExch(&g_ctr, 0);  // reset for next graph replay
        }
    }
}

extern "C" void kernel_launch(void* const* d_in, const int* in_sizes, int n_in,
                              void* d_out, int out_size) {
    (void)in_sizes; (void)n_in; (void)out_size;
    const float* x = (const float*)d_in[0];
    float* out = (float*)d_out;

    btv_kernel<<<GRIDB, dim3(BX, BY)>>>(x, out);
}

// round 12
// speedup vs baseline: 1.0457x; 1.0457x over previous
#include <cuda_runtime.h>
#include <cuda_fp16.h>

#define H 1024
#define W 1024
#define PLANES 24              // 8 * 3
#define THRAW 64               // raw output rows per tile
#define PACK 32                // row-pack stride (.x = r, .y = r+32)
#define TW 128                 // tile cols
#define RE 8                   // cols per thread
#define BX 16
#define BYW 32                 // packed rows per tile (= threads y)
#define THREADS (BX * BYW)     // 512
#define PROWS (BYW + 3)        // 35
#define SCOLS (TW + 8)         // 136 half2 = 34 16B-chunks per row
#define NBX (W / TW)           // 8
#define NBY (H / THRAW)        // 16
#define NT (NBX * NBY * PLANES)       // 3072 tiles
#define GRIDB 296              // 148 SMs x 2 resident blocks: persistent grid
#define NGRP (PROWS * (TW / 4))       // 1120 interior float4-groups
#define NHALO (PROWS * 8)             // 280 halo half2 entries

// Even/odd chunk de-interleave: physical slot i (0..31 interior) holds logical
// gmem float4 group QPERM(i). Window LDS.128s become lane-contiguous.
#define QPERM(i) (((i) < 16) ? (2 * (i) + 1) : (2 * ((i) - 16)))

__device__ float g_partials[GRIDB];
__device__ int g_ctr = 0;

// Full 16-half2 window (physical chunks tx, 17+tx, tx+1, 18+tx).
#define LOADROW(wdst, srow, txv)                                                   \
    do {                                                                           \
        const float4* rowp = reinterpret_cast<const float4*>(&(srow)[0]);          \
        float4 v0 = rowp[(txv)];                                                   \
        float4 v1 = rowp[17 + (txv)];                                              \
        float4 v2 = rowp[(txv) + 1];                                               \
        float4 v3 = rowp[18 + (txv)];                                              \
        (wdst)[0] = *(__half2*)&v0.x;  (wdst)[1] = *(__half2*)&v0.y;               \
        (wdst)[2] = *(__half2*)&v0.z;  (wdst)[3] = *(__half2*)&v0.w;               \
        (wdst)[4] = *(__half2*)&v1.x;  (wdst)[5] = *(__half2*)&v1.y;               \
        (wdst)[6] = *(__half2*)&v1.z;  (wdst)[7] = *(__half2*)&v1.w;               \
        (wdst)[8] = *(__half2*)&v2.x;  (wdst)[9] = *(__half2*)&v2.y;               \
        (wdst)[10] = *(__half2*)&v2.z; (wdst)[11] = *(__half2*)&v2.w;              \
        (wdst)[12] = *(__half2*)&v3.x; (wdst)[13] = *(__half2*)&v3.y;              \
        (wdst)[14] = *(__half2*)&v3.z; (wdst)[15] = *(__half2*)&v3.w;              \
    } while (0)

// k=0 needs only w[4..15] (dl >= 0): 3 LDS.128.
#define LOADROW_K0(wdst, srow, txv)                                                \
    do {                                                                           \
        const float4* rowp = reinterpret_cast<const float4*>(&(srow)[0]);          \
        float4 v1 = rowp[17 + (txv)];                                              \
        float4 v2 = rowp[(txv) + 1];                                               \
        float4 v3 = rowp[18 + (txv)];                                              \
        (wdst)[4] = *(__half2*)&v1.x;  (wdst)[5] = *(__half2*)&v1.y;               \
        (wdst)[6] = *(__half2*)&v1.z;  (wdst)[7] = *(__half2*)&v1.w;               \
        (wdst)[8] = *(__half2*)&v2.x;  (wdst)[9] = *(__half2*)&v2.y;               \
        (wdst)[10] = *(__half2*)&v2.z; (wdst)[11] = *(__half2*)&v2.w;              \
        (wdst)[12] = *(__half2*)&v3.x; (wdst)[13] = *(__half2*)&v3.y;              \
        (wdst)[14] = *(__half2*)&v3.z; (wdst)[15] = *(__half2*)&v3.w;              \
    } while (0)

// Phase A: physical slots [0, 1024) — unguarded (tid, tid+512 < 1024).
#define PREF_A(tt)                                                                 \
    do {                                                                           \
        int px_ = (tt) & (NBX - 1), py_ = ((tt) >> 3) & (NBY - 1), pz_ = (tt) >> 7; \
        int txx = px_ * TW, tyy = py_ * THRAW;                                     \
        const float4* pp = reinterpret_cast<const float4*>(x + (size_t)pz_ * (H * W)); \
        int g0 = tid, g1 = tid + 512;                                              \
        int r0 = g0 >> 5, i0 = g0 & 31, r1 = g1 >> 5, i1 = g1 & 31;                \
        int q0 = QPERM(i0), q1 = QPERM(i1);                                        \
        aA0 = pp[(((tyy + r0) & (H - 1)) * (W / 4)) + (txx >> 2) + q0];            \
        bA0 = pp[(((tyy + r0 + PACK) & (H - 1)) * (W / 4)) + (txx >> 2) + q0];     \
        aA1 = pp[(((tyy + r1) & (H - 1)) * (W / 4)) + (txx >> 2) + q1];            \
        bA1 = pp[(((tyy + r1 + PACK) & (H - 1)) * (W / 4)) + (txx >> 2) + q1];     \
    } while (0)

#define STORE_A(buf)                                                               \
    do {                                                                           \
        int g0 = tid, g1 = tid + 512;                                              \
        int r0 = g0 >> 5, i0 = g0 & 31, r1 = g1 >> 5, i1 = g1 & 31;                \
        __half2 h0 = __floats2half2_rn(aA0.x, bA0.x);                              \
        __half2 h1 = __floats2half2_rn(aA0.y, bA0.y);                              \
        __half2 h2 = __floats2half2_rn(aA0.z, bA0.z);                              \
        __half2 h3 = __floats2half2_rn(aA0.w, bA0.w);                              \
        float4 st0;                                                                \
        st0.x = *(float*)&h0; st0.y = *(float*)&h1;                                \
        st0.z = *(float*)&h2; st0.w = *(float*)&h3;                                \
        *reinterpret_cast<float4*>(&s[buf][r0][4 + 4 * i0]) = st0;                 \
        h0 = __floats2half2_rn(aA1.x, bA1.x);                                      \
        h1 = __floats2half2_rn(aA1.y, bA1.y);                                      \
        h2 = __floats2half2_rn(aA1.z, bA1.z);                                      \
        h3 = __floats2half2_rn(aA1.w, bA1.w);                                      \
        float4 st1;                                                                \
        st1.x = *(float*)&h0; st1.y = *(float*)&h1;                                \
        st1.z = *(float*)&h2; st1.w = *(float*)&h3;                                \
        *reinterpret_cast<float4*>(&s[buf][r1][4 + 4 * i1]) = st1;                 \
    } while (0)

// Phase B: physical slots [1024, 1120) + halo.
#define PREF_B(tt)                                                                 \
    do {                                                                           \
        int px_ = (tt) & (NBX - 1), py_ = ((tt) >> 3) & (NBY - 1), pz_ = (tt) >> 7; \
        int txx = px_ * TW, tyy = py_ * THRAW;                                     \
        const float* pl = x + (size_t)pz_ * (H * W);                               \
        const float4* pp = reinterpret_cast<const float4*>(pl);                    \
        if (tid < NGRP - 1024) {                                                   \
            int g = tid + 1024;                                                    \
            int r = g >> 5, i = g & 31;                                            \
            int q = QPERM(i);                                                      \
            aB = pp[(((tyy + r) & (H - 1)) * (W / 4)) + (txx >> 2) + q];           \
            bB = pp[(((tyy + r + PACK) & (H - 1)) * (W / 4)) + (txx >> 2) + q];    \
        }                                                                          \
        if (tid < NHALO) {                                                         \
            int r = tid >> 3, hcp = tid & 7;                                       \
            int c = (hcp < 4) ? hcp : (128 + hcp);                                 \
            int gc = (txx + c - 4) & (W - 1);                                      \
            pha = pl[(((tyy + r) & (H - 1)) * W) + gc];                            \
            phb = pl[(((tyy + r + PACK) & (H - 1)) * W) + gc];                     \
        }                                                                          \
    } while (0)

#define STORE_B(buf)                                                               \
    do {                                                                           \
        if (tid < NGRP - 1024) {                                                   \
            int g = tid + 1024;                                                    \
            int r = g >> 5, i = g & 31;                                            \
            __half2 h0 = __floats2half2_rn(aB.x, bB.x);                            \
            __half2 h1 = __floats2half2_rn(aB.y, bB.y);                            \
            __half2 h2 = __floats2half2_rn(aB.z, bB.z);                            \
            __half2 h3 = __floats2half2_rn(aB.w, bB.w);                            \
            float4 st;                                                             \
            st.x = *(float*)&h0; st.y = *(float*)&h1;                              \
            st.z = *(float*)&h2; st.w = *(float*)&h3;                              \
            *reinterpret_cast<float4*>(&s[buf][r][4 + 4 * i]) = st;                \
        }                                                                          \
        if (tid < NHALO) {                                                         \
            int r = tid >> 3, hcp = tid & 7;                                       \
            int c = (hcp < 4) ? hcp : (128 + hcp);                                 \
            s[buf][r][c] = __floats2half2_rn(pha, phb);                            \
        }                                                                          \
    } while (0)

#define KROW(row)                                                                  \
    do {                                                                           \
        __half2 win[16];                                                           \
        LOADROW(win, s[cb][row], tx);                                              \
        _Pragma("unroll")                                                          \
        for (int dl = -3; dl <= 3; dl++) {                                         \
            _Pragma("unroll")                                                      \
            for (int e = 0; e < RE; e++) {                                         \
                __half2 d = __habs2(__hsub2(c2[e], win[4 + e + dl]));              \
                acc[e] = __hadd2(acc[e], d);                                       \
            }                                                                      \
        }                                                                          \
    } while (0)

__global__ __launch_bounds__(THREADS, 2) void btv_kernel(const float* __restrict__ x,
                                                         float* __restrict__ out) {
    __shared__ __align__(16) __half2 s[2][PROWS][SCOLS];
    __shared__ float warp_sums[THREADS / 32];
    __shared__ int s_last;

    const int tx = threadIdx.x;
    const int ty = threadIdx.y;
    const int tid = ty * BX + tx;

    float4 aA0, aA1, bA0, bA1, aB, bB;
    float pha = 0.0f, phb = 0.0f;
    float accf = 0.0f;

    int t = blockIdx.x;

    // Prologue: first tile into buffer 0.
    PREF_A(t);
    STORE_A(0);
    PREF_B(t);
    STORE_B(0);
    __syncthreads();

    int cb = 0;
#pragma unroll 1
    for (; t < NT; t += GRIDB) {
        const int tn = t + GRIDB;
        const bool hn = (tn < NT);

        if (hn) PREF_A(tn);

        __half2 c2[RE];
        __half2 acc[RE];
#pragma unroll
        for (int e = 0; e < RE; e++) acc[e] = __floats2half2_rn(0.0f, 0.0f);

        // k = 0: centers + dl = 1..3 (symmetry covers negatives); 3 LDS only.
        {
            __half2 win[16];
            LOADROW_K0(win, s[cb][ty], tx);
#pragma unroll
            for (int e = 0; e < RE; e++) c2[e] = win[4 + e];
#pragma unroll
            for (int dl = 1; dl <= 3; dl++) {
#pragma unroll
                for (int e = 0; e < RE; e++) {
                    __half2 d = __habs2(__hsub2(c2[e], win[4 + e + dl]));
                    acc[e] = __hadd2(acc[e], d);
                }
            }
        }

        KROW(ty + 1);   // k = 1

        if (hn) {
            STORE_A(cb ^ 1);
            PREF_B(tn);
        }

        KROW(ty + 2);   // k = 2
        KROW(ty + 3);   // k = 3

        // Drain fp16 accumulators to fp32 per tile.
#pragma unroll
        for (int e = 0; e < RE; e++) {
            float2 f = __half22float2(acc[e]);
            accf += f.x + f.y;
        }

        if (hn) {
            STORE_B(cb ^ 1);
            __syncthreads();
        }
        cb ^= 1;
    }

    // ---- Block reduction ----
#pragma unroll
    for (int o = 16; o > 0; o >>= 1) accf += __shfl_down_sync(0xFFFFFFFFu, accf, o);

    const int lane = tid & 31;
    const int wid = tid >> 5;
    if (lane == 0) warp_sums[wid] = accf;
    __syncthreads();

    if (tid == 0) {
        float bsum = 0.0f;
#pragma unroll
        for (int i = 0; i < THREADS / 32; i++) bsum += warp_sums[i];
        g_partials[blockIdx.x] = bsum;
        __threadfence();
        int done = atomicAdd(&g_ctr, 1);
        s_last = (done == GRIDB - 1) ? 1 : 0;
    }
    __syncthreads();

    // Last block reduces all partials (fixed order -> deterministic)
    if (s_last) {
        double td = 0.0;
        for (int i = tid; i < GRIDB; i += THREADS) td += (double)g_partials[i];
#pragma unroll
        for (int o = 16; o > 0; o >>= 1) td += __shfl_down_sync(0xFFFFFFFFu, td, o);
        __shared__ double sm[THREADS / 32];
        if (lane == 0) sm[wid] = td;
        __syncthreads();
        if (tid == 0) {
            double r = 0.0;
#pragma unroll
            for (int i = 0; i < THREADS / 32; i++) r += sm[i];
            // symmetry factor 2; WEIGHT=0.1; N = 24*1024*1024
            out[0] = (float)(r * (0.2 / 25165824.0));
            atomicExch(&g_ctr, 0);  // reset for next graph replay
        }
    }
}

extern "C" void kernel_launch(void* const* d_in, const int* in_sizes, int n_in,
                              void* d_out, int out_size) {
    (void)in_sizes; (void)n_in; (void)out_size;
    const float* x = (const float*)d_in[0];
    float* out = (float*)d_out;

    btv_kernel<<<GRIDB, dim3(BX, BYW)>>>(x, out);
}